// round 16
// baseline (speedup 1.0000x reference)
#include <cuda_runtime.h>
#include <cuda_bf16.h>
#include <cuda_fp16.h>
#include <math.h>
#include <stdint.h>

// ---------------------------------------------------------------------------
// Problem constants
// ---------------------------------------------------------------------------
#define N_NODES_MAX 20000
#define N_EDGES_MAX 320000
#define DIN 256
#define D1 128
#define D2 64
#define D3 128
#define D4 64
#define NCLS 10

// ---------------------------------------------------------------------------
// Scratch (static device globals; no allocations anywhere)
// ---------------------------------------------------------------------------
__device__ __half g_XRh [N_NODES_MAX * D1];    // fp16 conv1 rel output
__device__ float  g_H1  [N_NODES_MAX * D1];
__device__ __half g_XR2h[N_NODES_MAX * D2];    // fp16 conv2 rel output
__device__ float  g_H2  [N_NODES_MAX * D2];

// CSR (built per launch): rowptr[v]..rowptr[v+1] = in-edges of node v
__device__ int g_rowptr[N_NODES_MAX + 1];
__device__ int g_cursor[N_NODES_MAX];
__device__ int g_srcidx[N_EDGES_MAX];

// bf16 hi/lo weights, transposed to [n][k] K-major
__device__ __nv_bfloat16 g_B1hi[2 * D1 * DIN];
__device__ __nv_bfloat16 g_B1lo[2 * D1 * DIN];
__device__ __nv_bfloat16 g_B2hi[128 * 128];
__device__ __nv_bfloat16 g_B2lo[128 * 128];
__device__ __nv_bfloat16 g_B3hi[128 * 64];
__device__ __nv_bfloat16 g_B3lo[128 * 64];
__device__ __nv_bfloat16 g_B4hi[64 * 128];
__device__ __nv_bfloat16 g_B4lo[64 * 128];

// ---------------------------------------------------------------------------
// mma.sync helpers
// ---------------------------------------------------------------------------
__device__ __forceinline__ uint32_t smem_u32(const void* p) {
    uint32_t a;
    asm("{ .reg .u64 t; cvta.to.shared.u64 t, %1; cvt.u32.u64 %0, t; }"
        : "=r"(a) : "l"(p));
    return a;
}
__device__ __forceinline__ void ldsm_x4(uint32_t& r0, uint32_t& r1,
                                        uint32_t& r2, uint32_t& r3,
                                        uint32_t addr) {
    asm volatile("ldmatrix.sync.aligned.m8n8.x4.shared.b16 {%0,%1,%2,%3}, [%4];"
                 : "=r"(r0), "=r"(r1), "=r"(r2), "=r"(r3) : "r"(addr));
}
__device__ __forceinline__ void mma_bf16(float& c0, float& c1, float& c2, float& c3,
                                         uint32_t a0, uint32_t a1, uint32_t a2, uint32_t a3,
                                         uint32_t b0, uint32_t b1) {
    asm volatile(
        "mma.sync.aligned.m16n8k16.row.col.f32.bf16.bf16.f32 "
        "{%0,%1,%2,%3}, {%4,%5,%6,%7}, {%8,%9}, {%0,%1,%2,%3};"
        : "+f"(c0), "+f"(c1), "+f"(c2), "+f"(c3)
        : "r"(a0), "r"(a1), "r"(a2), "r"(a3), "r"(b0), "r"(b1));
}

// ---------------------------------------------------------------------------
// CSR build kernels
// ---------------------------------------------------------------------------
__global__ void csr_zero_kernel(int N)
{
    int i = blockIdx.x * blockDim.x + threadIdx.x;
    if (i <= N) g_rowptr[i] = 0;
}

__global__ void csr_hist_kernel(const int* __restrict__ ei, int nE)
{
    int e = blockIdx.x * blockDim.x + threadIdx.x;
    if (e < nE) atomicAdd(&g_rowptr[ei[nE + e]], 1);
}

// single block, 1024 threads: exclusive scan of counts -> rowptr, copy cursor
__global__ void __launch_bounds__(1024)
csr_scan_kernel(int N)
{
    __shared__ int warpsum[32];
    const int tid = threadIdx.x;
    const int CH = (N + 1023) / 1024;
    const int lo = min(tid * CH, N);
    const int hi = min(lo + CH, N);

    int s = 0;
    for (int i = lo; i < hi; i++) s += g_rowptr[i];

    const int lane = tid & 31, wid = tid >> 5;
    int v = s;
    #pragma unroll
    for (int o = 1; o < 32; o <<= 1) {
        int t = __shfl_up_sync(0xffffffffu, v, o);
        if (lane >= o) v += t;
    }
    if (lane == 31) warpsum[wid] = v;
    __syncthreads();
    if (wid == 0) {
        int w = warpsum[lane];
        #pragma unroll
        for (int o = 1; o < 32; o <<= 1) {
            int t = __shfl_up_sync(0xffffffffu, w, o);
            if (lane >= o) w += t;
        }
        warpsum[lane] = w;
    }
    __syncthreads();

    int run = v - s + (wid > 0 ? warpsum[wid - 1] : 0);
    for (int i = lo; i < hi; i++) {
        int cnt = g_rowptr[i];
        g_rowptr[i] = run;
        g_cursor[i] = run;
        run += cnt;
    }
    if (hi == N) g_rowptr[N] = run;   // all qualifying threads write the total
}

__global__ void csr_permute_kernel(const int* __restrict__ ei, int nE)
{
    int e = blockIdx.x * blockDim.x + threadIdx.x;
    if (e >= nE) return;
    int d = ei[nE + e];
    int pos = atomicAdd(&g_cursor[d], 1);
    g_srcidx[pos] = ei[e];
}

// ---------------------------------------------------------------------------
// CSR gathers: one warp per node, register accumulation, single row write.
// ---------------------------------------------------------------------------
__global__ void __launch_bounds__(256)
gather_add128_kernel(const __half* __restrict__ src, float* __restrict__ dst,
                     int M)
{
    int v = blockIdx.x * 8 + (threadIdx.x >> 5);
    if (v >= M) return;
    const int lane = threadIdx.x & 31;
    const int s = g_rowptr[v], e = g_rowptr[v + 1];

    float* dp = dst + (size_t)v * 128 + lane * 4;
    float4 acc = *(float4*)dp;

    int j = s;
    for (; j + 4 <= e; j += 4) {
        int i0 = g_srcidx[j], i1 = g_srcidx[j + 1];
        int i2 = g_srcidx[j + 2], i3 = g_srcidx[j + 3];
        uint2 v0 = *(const uint2*)(src + (size_t)i0 * 128 + lane * 4);
        uint2 v1 = *(const uint2*)(src + (size_t)i1 * 128 + lane * 4);
        uint2 v2 = *(const uint2*)(src + (size_t)i2 * 128 + lane * 4);
        uint2 v3 = *(const uint2*)(src + (size_t)i3 * 128 + lane * 4);
        #pragma unroll
        for (int q = 0; q < 4; q++) {
            uint2 vv = (q == 0) ? v0 : (q == 1) ? v1 : (q == 2) ? v2 : v3;
            float2 a = __half22float2(*(__half2*)&vv.x);
            float2 b = __half22float2(*(__half2*)&vv.y);
            acc.x += a.x; acc.y += a.y; acc.z += b.x; acc.w += b.y;
        }
    }
    for (; j < e; j++) {
        int i0 = g_srcidx[j];
        uint2 vv = *(const uint2*)(src + (size_t)i0 * 128 + lane * 4);
        float2 a = __half22float2(*(__half2*)&vv.x);
        float2 b = __half22float2(*(__half2*)&vv.y);
        acc.x += a.x; acc.y += a.y; acc.z += b.x; acc.w += b.y;
    }
    *(float4*)dp = acc;
}

__global__ void __launch_bounds__(256)
gather_add64_kernel(const __half* __restrict__ src, float* __restrict__ dst,
                    int M)
{
    int v = blockIdx.x * 8 + (threadIdx.x >> 5);
    if (v >= M) return;
    const int lane = threadIdx.x & 31;
    const int s = g_rowptr[v], e = g_rowptr[v + 1];

    float* dp = dst + (size_t)v * 64 + lane * 2;
    float2 acc = *(float2*)dp;

    int j = s;
    for (; j + 4 <= e; j += 4) {
        int i0 = g_srcidx[j], i1 = g_srcidx[j + 1];
        int i2 = g_srcidx[j + 2], i3 = g_srcidx[j + 3];
        uint32_t v0 = *(const uint32_t*)(src + (size_t)i0 * 64 + lane * 2);
        uint32_t v1 = *(const uint32_t*)(src + (size_t)i1 * 64 + lane * 2);
        uint32_t v2 = *(const uint32_t*)(src + (size_t)i2 * 64 + lane * 2);
        uint32_t v3 = *(const uint32_t*)(src + (size_t)i3 * 64 + lane * 2);
        #pragma unroll
        for (int q = 0; q < 4; q++) {
            uint32_t vv = (q == 0) ? v0 : (q == 1) ? v1 : (q == 2) ? v2 : v3;
            float2 a = __half22float2(*(__half2*)&vv);
            acc.x += a.x; acc.y += a.y;
        }
    }
    for (; j < e; j++) {
        uint32_t vv = *(const uint32_t*)(src + (size_t)g_srcidx[j] * 64 + lane * 2);
        float2 a = __half22float2(*(__half2*)&vv);
        acc.x += a.x; acc.y += a.y;
    }
    *(float2*)dp = acc;
}

// ---------------------------------------------------------------------------
// Combined weight prep: fp32 -> bf16 hi/lo, transposed to [n][k]
// ---------------------------------------------------------------------------
#define NW1 (2 * DIN * D1)      // 65536
#define NW2 (128 * 128)         // 16384
#define NW3 (128 * 64)          // 8192
#define NW4 (64 * 128)          // 8192
__global__ void prep_weights_kernel(const float* __restrict__ W1rel,
                                    const float* __restrict__ W1rt,
                                    const float* __restrict__ W2rel,
                                    const float* __restrict__ W2rt,
                                    const float* __restrict__ L1w,
                                    const float* __restrict__ L2w)
{
    int idx = blockIdx.x * blockDim.x + threadIdx.x;
    float f;
    __nv_bfloat16* dh;
    __nv_bfloat16* dl;
    size_t off;
    if (idx < NW1) {
        int w   = idx / (DIN * D1);
        int rem = idx % (DIN * D1);
        int k   = rem / D1;
        int n   = rem % D1;
        f   = (w ? W1rt : W1rel)[k * D1 + n];
        off = (size_t)w * D1 * DIN + (size_t)n * DIN + k;
        dh = g_B1hi; dl = g_B1lo;
    } else if (idx < NW1 + NW2) {
        int i = idx - NW1;
        int n = i / 128;
        int k = i % 128;
        f   = (n < 64) ? W2rel[k * 64 + n] : W2rt[k * 64 + (n - 64)];
        off = (size_t)n * 128 + k;
        dh = g_B2hi; dl = g_B2lo;
    } else if (idx < NW1 + NW2 + NW3) {
        int i = idx - NW1 - NW2;
        int n = i / 64;
        int k = i % 64;
        f   = L1w[k * 128 + n];
        off = (size_t)n * 64 + k;
        dh = g_B3hi; dl = g_B3lo;
    } else if (idx < NW1 + NW2 + NW3 + NW4) {
        int i = idx - NW1 - NW2 - NW3;
        int n = i / 128;
        int k = i % 128;
        f   = L2w[k * 64 + n];
        off = (size_t)n * 128 + k;
        dh = g_B4hi; dl = g_B4lo;
    } else return;

    __nv_bfloat16 h = __float2bfloat16(f);
    dh[off] = h;
    dl[off] = __float2bfloat16(f - __bfloat162float(h));
}

// ---------------------------------------------------------------------------
// Pipelined mma core (register prefetch, 80B row stride => conflict-free
// ldmatrix). BM=64 (MT=2). NW in {2,4}. A row stride ASTRIDE floats.
// ---------------------------------------------------------------------------
template<int KDIM, int ASTRIDE, int MT, int NW, bool RELU_A>
__device__ __forceinline__ void mma_core(
    char* smem, uint32_t sbase,
    const float* __restrict__ A,
    const __nv_bfloat16* __restrict__ Bh,
    const __nv_bfloat16* __restrict__ Bl,
    int rowBase, int M,
    float c[MT][NW][4])
{
    constexpr int BM = 2 * MT * 16;
    static_assert(BM == 64, "core assumes BM=64");
    constexpr int BN = 4 * NW * 8;
    constexpr int RS = 80;
    constexpr int OFF_AL = BM * RS;
    constexpr int OFF_BH = 2 * BM * RS;
    constexpr int OFF_BL = 2 * BM * RS + BN * RS;
    constexpr int BIT = BN / 64;
    constexpr int NCH = KDIM / 32;

    const int tid  = threadIdx.x;
    const int wid  = tid >> 5;
    const int lane = tid & 31;

    const int mBase = (wid >> 2) * (MT * 16);
    const int nBase = (wid & 3) * (NW * 8);

    const int qr    = lane & 7;
    const int half1 = (lane >> 3) & 1;
    const int half2 = (lane >> 4) & 1;

    const int rA  = tid >> 2;
    const int kcA = tid & 3;
    const int gA  = rowBase + rA;

    float aR[8];
    uint4 bhR[BIT], blR[BIT];

    {
        if (gA < M) {
            const float* ap = A + (size_t)gA * ASTRIDE + kcA * 8;
            float4 x0 = *(const float4*)ap;
            float4 x1 = *(const float4*)(ap + 4);
            aR[0]=x0.x; aR[1]=x0.y; aR[2]=x0.z; aR[3]=x0.w;
            aR[4]=x1.x; aR[5]=x1.y; aR[6]=x1.z; aR[7]=x1.w;
        } else {
            #pragma unroll
            for (int j = 0; j < 8; j++) aR[j] = 0.f;
        }
        #pragma unroll
        for (int it = 0; it < BIT; it++) {
            int i = tid + it * 256;
            int r = i >> 2, kc = i & 3;
            bhR[it] = *(const uint4*)(Bh + (size_t)r * KDIM + kc * 8);
            blR[it] = *(const uint4*)(Bl + (size_t)r * KDIM + kc * 8);
        }
    }

    for (int ch = 0; ch < NCH; ch++) {
        {
            __nv_bfloat16 h[8], l[8];
            #pragma unroll
            for (int j = 0; j < 8; j++) {
                float fv = RELU_A ? fmaxf(aR[j], 0.f) : aR[j];
                h[j] = __float2bfloat16(fv);
                l[j] = __float2bfloat16(fv - __bfloat162float(h[j]));
            }
            uint32_t soA = (uint32_t)(rA * RS + kcA * 16);
            *(uint4*)(smem + soA) = *(uint4*)h;
            *(uint4*)(smem + OFF_AL + soA) = *(uint4*)l;
            #pragma unroll
            for (int it = 0; it < BIT; it++) {
                int i = tid + it * 256;
                int r = i >> 2, kc = i & 3;
                uint32_t soB = (uint32_t)(r * RS + kc * 16);
                *(uint4*)(smem + OFF_BH + soB) = bhR[it];
                *(uint4*)(smem + OFF_BL + soB) = blR[it];
            }
        }
        __syncthreads();

        if (ch + 1 < NCH) {
            const int k0 = (ch + 1) * 32;
            if (gA < M) {
                const float* ap = A + (size_t)gA * ASTRIDE + k0 + kcA * 8;
                float4 x0 = *(const float4*)ap;
                float4 x1 = *(const float4*)(ap + 4);
                aR[0]=x0.x; aR[1]=x0.y; aR[2]=x0.z; aR[3]=x0.w;
                aR[4]=x1.x; aR[5]=x1.y; aR[6]=x1.z; aR[7]=x1.w;
            } else {
                #pragma unroll
                for (int j = 0; j < 8; j++) aR[j] = 0.f;
            }
            #pragma unroll
            for (int it = 0; it < BIT; it++) {
                int i = tid + it * 256;
                int r = i >> 2, kc = i & 3;
                bhR[it] = *(const uint4*)(Bh + (size_t)r * KDIM + k0 + kc * 8);
                blR[it] = *(const uint4*)(Bl + (size_t)r * KDIM + k0 + kc * 8);
            }
        }

        #pragma unroll
        for (int ks = 0; ks < 2; ks++) {
            uint32_t ah[MT][4], al[MT][4];
            #pragma unroll
            for (int mt = 0; mt < MT; mt++) {
                int r = mBase + mt * 16 + qr + half1 * 8;
                uint32_t so = (uint32_t)(r * RS + (ks * 2 + half2) * 16);
                ldsm_x4(ah[mt][0], ah[mt][1], ah[mt][2], ah[mt][3], sbase + so);
                ldsm_x4(al[mt][0], al[mt][1], al[mt][2], al[mt][3],
                        sbase + OFF_AL + so);
            }
            uint32_t bh[NW / 2][4], bl[NW / 2][4];
            #pragma unroll
            for (int pr = 0; pr < NW / 2; pr++) {
                int r = nBase + pr * 16 + qr + half2 * 8;
                uint32_t so = (uint32_t)(r * RS + (ks * 2 + half1) * 16);
                ldsm_x4(bh[pr][0], bh[pr][1], bh[pr][2], bh[pr][3],
                        sbase + OFF_BH + so);
                ldsm_x4(bl[pr][0], bl[pr][1], bl[pr][2], bl[pr][3],
                        sbase + OFF_BL + so);
            }
            #pragma unroll
            for (int mt = 0; mt < MT; mt++) {
                #pragma unroll
                for (int nt = 0; nt < NW; nt++) {
                    uint32_t b0h = bh[nt >> 1][(nt & 1) * 2];
                    uint32_t b1h = bh[nt >> 1][(nt & 1) * 2 + 1];
                    uint32_t b0l = bl[nt >> 1][(nt & 1) * 2];
                    uint32_t b1l = bl[nt >> 1][(nt & 1) * 2 + 1];
                    float* cc = c[mt][nt];
                    mma_bf16(cc[0], cc[1], cc[2], cc[3],
                             ah[mt][0], ah[mt][1], ah[mt][2], ah[mt][3], b0h, b1h);
                    mma_bf16(cc[0], cc[1], cc[2], cc[3],
                             ah[mt][0], ah[mt][1], ah[mt][2], ah[mt][3], b0l, b1l);
                    mma_bf16(cc[0], cc[1], cc[2], cc[3],
                             al[mt][0], al[mt][1], al[mt][2], al[mt][3], b0h, b1h);
                }
            }
        }
        __syncthreads();
    }
}

// ---------------------------------------------------------------------------
// conv GEMM kernels.
//   MODE 0 (conv1): y==0 -> XRh (fp16, no bias); y==1 -> H1 (+b1), stride 128.
//   MODE 1 (conv2): cols<64 -> XR2h (fp16); cols>=64 -> H2 (+b2), stride 64.
// ---------------------------------------------------------------------------
template<int KDIM, int MODE, bool RELU_A>
__global__ void __launch_bounds__(256, 2)
mma_gemm_kernel(const float* __restrict__ A,
                const __nv_bfloat16* __restrict__ Bhi,
                const __nv_bfloat16* __restrict__ Blo,
                const float* __restrict__ bias,
                __half* __restrict__ C0h, float* __restrict__ C1, int M)
{
    constexpr int MT = 2, NW = 4;
    constexpr int BM = 64;
    constexpr int BN = 128;
    __shared__ char smem[2 * (BM + BN) * 80];   // 30720 B
    const uint32_t sbase = smem_u32(smem);

    const int wid  = threadIdx.x >> 5;
    const int lane = threadIdx.x & 31;
    const int rowBase = blockIdx.x * BM;

    const __nv_bfloat16* Bh = Bhi;
    const __nv_bfloat16* Bl = Blo;
    if (MODE == 0) {
        Bh += (size_t)blockIdx.y * 128 * KDIM;
        Bl += (size_t)blockIdx.y * 128 * KDIM;
    }

    float c[MT][NW][4];
    #pragma unroll
    for (int i = 0; i < MT; i++)
        #pragma unroll
        for (int j = 0; j < NW; j++)
            #pragma unroll
            for (int q = 0; q < 4; q++) c[i][j][q] = 0.f;

    mma_core<KDIM, KDIM, MT, NW, RELU_A>(smem, sbase, A, Bh, Bl, rowBase, M, c);

    const int mBase = (wid >> 2) * (MT * 16);
    const int nBase = (wid & 3) * (NW * 8);
    const int gid = lane >> 2;
    const int tig = lane & 3;
    #pragma unroll
    for (int mt = 0; mt < MT; mt++) {
        #pragma unroll
        for (int nt = 0; nt < NW; nt++) {
            int col  = nBase + nt * 8 + tig * 2;
            int row0 = rowBase + mBase + mt * 16 + gid;
            int row1 = row0 + 8;

            bool toF16 = (MODE == 0) ? (blockIdx.y == 0) : (col < 64);
            if (toF16) {
                int stride = (MODE == 0) ? 128 : 64;
                int ccol   = col;           // MODE 1: col already < 64
                if (row0 < M)
                    *(__half2*)(C0h + (size_t)row0 * stride + ccol) =
                        __floats2half2_rn(c[mt][nt][0], c[mt][nt][1]);
                if (row1 < M)
                    *(__half2*)(C0h + (size_t)row1 * stride + ccol) =
                        __floats2half2_rn(c[mt][nt][2], c[mt][nt][3]);
                continue;
            }

            int ccol   = (MODE == 0) ? col : (col - 64);
            int stride = (MODE == 0) ? 128 : 64;
            float bx = bias[ccol], by = bias[ccol + 1];
            if (row0 < M) {
                float2 v; v.x = c[mt][nt][0] + bx; v.y = c[mt][nt][1] + by;
                *(float2*)(C1 + (size_t)row0 * stride + ccol) = v;
            }
            if (row1 < M) {
                float2 v; v.x = c[mt][nt][2] + bx; v.y = c[mt][nt][3] + by;
                *(float2*)(C1 + (size_t)row1 * stride + ccol) = v;
            }
        }
    }
}

// ---------------------------------------------------------------------------
// Fused MLP (unchanged from R13)
// ---------------------------------------------------------------------------
#define FUSED_H3OFF   30720
#define FUSED_H3STR   132
#define FUSED_W3OFF   64512
#define FUSED_B3OFF   67072
#define FUSED_SMEM    67200
#define FUSED_CTSTR   68

__global__ void __launch_bounds__(256, 2)
mlp_fused_kernel(const float* __restrict__ A,
                 const __nv_bfloat16* __restrict__ B3hi,
                 const __nv_bfloat16* __restrict__ B3lo,
                 const float* __restrict__ L1b,
                 const __nv_bfloat16* __restrict__ B4hi,
                 const __nv_bfloat16* __restrict__ B4lo,
                 const float* __restrict__ L2b,
                 const float* __restrict__ W3,
                 const float* __restrict__ b3,
                 float* __restrict__ out, int M)
{
    extern __shared__ char dsm[];
    const uint32_t sbase = smem_u32(dsm);
    float* H3t = (float*)(dsm + FUSED_H3OFF);
    float* Ct  = (float*)(dsm + FUSED_H3OFF);
    float* W3s = (float*)(dsm + FUSED_W3OFF);
    float* b3s = (float*)(dsm + FUSED_B3OFF);

    const int tid  = threadIdx.x;
    const int wid  = tid >> 5;
    const int lane = tid & 31;
    const int rowBase = blockIdx.x * 64;
    const int Mloc = min(64, M - rowBase);

    for (int i = tid; i < D4 * NCLS; i += 256) W3s[i] = W3[i];
    if (tid < NCLS) b3s[tid] = b3[tid];

    const int mBase = (wid >> 2) * 32;
    const int gid = lane >> 2;
    const int tig = lane & 3;

    {
        float c1[2][4][4];
        #pragma unroll
        for (int i = 0; i < 2; i++)
            #pragma unroll
            for (int j = 0; j < 4; j++)
                #pragma unroll
                for (int q = 0; q < 4; q++) c1[i][j][q] = 0.f;

        mma_core<64, 64, 2, 4, false>(dsm, sbase, A, B3hi, B3lo, rowBase, M, c1);

        const int nBase = (wid & 3) * 32;
        #pragma unroll
        for (int mt = 0; mt < 2; mt++) {
            #pragma unroll
            for (int nt = 0; nt < 4; nt++) {
                int col = nBase + nt * 8 + tig * 2;
                int r0  = mBase + mt * 16 + gid;
                float bx = L1b[col], by = L1b[col + 1];
                float2 v0, v1;
                v0.x = fmaxf(c1[mt][nt][0] + bx, 0.f);
                v0.y = fmaxf(c1[mt][nt][1] + by, 0.f);
                v1.x = fmaxf(c1[mt][nt][2] + bx, 0.f);
                v1.y = fmaxf(c1[mt][nt][3] + by, 0.f);
                *(float2*)(H3t + (size_t)r0 * FUSED_H3STR + col) = v0;
                *(float2*)(H3t + (size_t)(r0 + 8) * FUSED_H3STR + col) = v1;
            }
        }
    }
    __syncthreads();

    float c2[2][2][4];
    #pragma unroll
    for (int i = 0; i < 2; i++)
        #pragma unroll
        for (int j = 0; j < 2; j++)
            #pragma unroll
            for (int q = 0; q < 4; q++) c2[i][j][q] = 0.f;

    mma_core<128, FUSED_H3STR, 2, 2, false>(dsm, sbase, H3t, B4hi, B4lo,
                                            0, Mloc, c2);

    {
        const int nBase = (wid & 3) * 16;
        #pragma unroll
        for (int mt = 0; mt < 2; mt++) {
            #pragma unroll
            for (int nt = 0; nt < 2; nt++) {
                int col = nBase + nt * 8 + tig * 2;
                int r0  = mBase + mt * 16 + gid;
                float bx = L2b[col], by = L2b[col + 1];
                Ct[(size_t)r0 * FUSED_CTSTR + col]           = fmaxf(c2[mt][nt][0] + bx, 0.f);
                Ct[(size_t)r0 * FUSED_CTSTR + col + 1]       = fmaxf(c2[mt][nt][1] + by, 0.f);
                Ct[(size_t)(r0 + 8) * FUSED_CTSTR + col]     = fmaxf(c2[mt][nt][2] + bx, 0.f);
                Ct[(size_t)(r0 + 8) * FUSED_CTSTR + col + 1] = fmaxf(c2[mt][nt][3] + by, 0.f);
            }
        }
    }
    __syncthreads();

    #pragma unroll
    for (int rr = 0; rr < 8; rr++) {
        int r  = wid * 8 + rr;
        int gr = rowBase + r;
        if (gr >= M) continue;

        float acc2 = -1e30f;
        if (lane < NCLS) {
            acc2 = b3s[lane];
            #pragma unroll 8
            for (int k = 0; k < D4; k++)
                acc2 = fmaf(Ct[(size_t)r * FUSED_CTSTR + k], W3s[k * NCLS + lane], acc2);
        }
        float m = acc2;
        #pragma unroll
        for (int o = 16; o > 0; o >>= 1)
            m = fmaxf(m, __shfl_xor_sync(0xffffffffu, m, o));
        float ex = (lane < NCLS) ? expf(acc2 - m) : 0.f;
        float ssum = ex;
        #pragma unroll
        for (int o = 16; o > 0; o >>= 1)
            ssum += __shfl_xor_sync(0xffffffffu, ssum, o);
        float lse = m + logf(ssum);
        if (lane < NCLS)
            out[(size_t)gr * NCLS + lane] = acc2 - lse;
    }
}

// ---------------------------------------------------------------------------
// Launch
// ---------------------------------------------------------------------------
extern "C" void kernel_launch(void* const* d_in, const int* in_sizes, int n_in,
                              void* d_out, int out_size)
{
    const float* x      = (const float*)d_in[0];
    const int*   ei     = (const int*)d_in[1];
    const float* W1_rel = (const float*)d_in[2];
    const float* W1_rt  = (const float*)d_in[3];
    const float* b1     = (const float*)d_in[4];
    const float* W2_rel = (const float*)d_in[5];
    const float* W2_rt  = (const float*)d_in[6];
    const float* b2     = (const float*)d_in[7];
    const float* L1w    = (const float*)d_in[8];
    const float* L1b    = (const float*)d_in[9];
    const float* L2w    = (const float*)d_in[10];
    const float* L2b    = (const float*)d_in[11];
    const float* L3w    = (const float*)d_in[12];
    const float* L3b    = (const float*)d_in[13];
    float*       out    = (float*)d_out;

    const int M  = in_sizes[0] / DIN;   // 20000
    const int nE = in_sizes[1] / 2;     // 320000

    __half *XRh, *XR2h;
    float *H1, *H2;
    __nv_bfloat16 *B1hi, *B1lo, *B2hi, *B2lo, *B3hi, *B3lo, *B4hi, *B4lo;
    cudaGetSymbolAddress((void**)&XRh,  g_XRh);
    cudaGetSymbolAddress((void**)&H1,   g_H1);
    cudaGetSymbolAddress((void**)&XR2h, g_XR2h);
    cudaGetSymbolAddress((void**)&H2,   g_H2);
    cudaGetSymbolAddress((void**)&B1hi, g_B1hi);
    cudaGetSymbolAddress((void**)&B1lo, g_B1lo);
    cudaGetSymbolAddress((void**)&B2hi, g_B2hi);
    cudaGetSymbolAddress((void**)&B2lo, g_B2lo);
    cudaGetSymbolAddress((void**)&B3hi, g_B3hi);
    cudaGetSymbolAddress((void**)&B3lo, g_B3lo);
    cudaGetSymbolAddress((void**)&B4hi, g_B4hi);
    cudaGetSymbolAddress((void**)&B4lo, g_B4lo);

    cudaFuncSetAttribute(mlp_fused_kernel,
                         cudaFuncAttributeMaxDynamicSharedMemorySize, FUSED_SMEM);

    const int gM64 = (M + 63) / 64;   // 313
    const int gNode8 = (M + 7) / 8;   // 2500

    // weight prep
    {
        int ntot = NW1 + NW2 + NW3 + NW4;
        prep_weights_kernel<<<(ntot + 255) / 256, 256>>>(W1_rel, W1_rt, W2_rel,
                                                         W2_rt, L1w, L2w);
    }

    // CSR build (independent of conv1; reused by both gathers)
    csr_zero_kernel<<<(M + 256) / 256, 256>>>(M);
    csr_hist_kernel<<<(nE + 255) / 256, 256>>>(ei, nE);
    csr_scan_kernel<<<1, 1024>>>(M);
    csr_permute_kernel<<<(nE + 255) / 256, 256>>>(ei, nE);

    // conv1: XRh = fp16(x@W1_rel) ; H1 = x@W1_root + b1
    mma_gemm_kernel<256, 0, false>
        <<<dim3(gM64, 2), 256>>>(x, B1hi, B1lo, b1, XRh, H1, M);

    // H1[v] += sum over in-edges of XRh[src]
    gather_add128_kernel<<<gNode8, 256>>>(XRh, H1, M);

    // conv2: XR2h = fp16(relu(H1)@W2_rel) ; H2 = relu(H1)@W2_root + b2
    mma_gemm_kernel<128, 1, true>
        <<<gM64, 256>>>(H1, B2hi, B2lo, b2, XR2h, H2, M);

    // H2[v] += sum over in-edges of XR2h[src]
    gather_add64_kernel<<<gNode8, 256>>>(XR2h, H2, M);

    // fused MLP: mlp1 + mlp2 + head
    mlp_fused_kernel<<<gM64, 256, FUSED_SMEM>>>(H2, B3hi, B3lo, L1b,
                                                B4hi, B4lo, L2b, L3w, L3b,
                                                out, M);
}